// round 1
// baseline (speedup 1.0000x reference)
#include <cuda_runtime.h>
#include <cstdint>

#define BB 512
#define SS 512
#define FF 64
#define HH 128
#define GG 512   // 4*H
#define OO 64

// ---- scratch (static __device__ globals: allocation-free rule) ----
__device__ float g_xp[(size_t)BB * SS * GG];   // 512 MB, reused for layer0 and layer1 projections
__device__ float g_h0[(size_t)BB * SS * HH];   // 64 MB  (layer0 hidden sequence)
__device__ float g_h1[BB * HH];                // layer1 last hidden

__device__ __forceinline__ float sigf(float x) {
    return __fdividef(1.0f, 1.0f + __expf(-x));
}
__device__ __forceinline__ float tanhf_fast(float x) {
    return 1.0f - __fdividef(2.0f, __expf(2.0f * x) + 1.0f);
}

// =====================================================================
// Projection GEMM: out[M, 512] = A[M, K] @ W[512, K]^T + ba[n] + bb[n]
// grid = (M/64, 512/256), block = 256. SMEM: As[K][64], Ws[K][256]
// =====================================================================
template <int K>
__global__ __launch_bounds__(256) void proj_kernel(
    const float* __restrict__ A, const float* __restrict__ W,
    const float* __restrict__ ba, const float* __restrict__ bb,
    float* __restrict__ out)
{
    extern __shared__ float sm[];
    float* As = sm;            // [K][64]
    float* Ws = sm + K * 64;   // [K][256]

    const int tid = threadIdx.x;
    const int m0 = blockIdx.x * 64;
    const int n0 = blockIdx.y * 256;

    // fill As (lanes along m -> conflict-free STS; global rows L1-sector reused)
    {
        const int r = tid & 63;
        for (int k = (tid >> 6); k < K; k += 4)
            As[k * 64 + r] = A[(size_t)(m0 + r) * K + k];
    }
    // fill Ws (lane = n column, walk k)
    {
        const float* wrow = W + (size_t)(n0 + tid) * K;
        #pragma unroll 4
        for (int k = 0; k < K; k++)
            Ws[k * 256 + tid] = wrow[k];
    }
    __syncthreads();

    const int tx = tid & 31, ty = tid >> 5;
    const int mb = ty * 8, nb = tx * 8;

    float acc[8][8];
    #pragma unroll
    for (int i = 0; i < 8; i++)
        #pragma unroll
        for (int j = 0; j < 8; j++) acc[i][j] = 0.0f;

    #pragma unroll 4
    for (int k = 0; k < K; k++) {
        float4 a0 = *(const float4*)(As + k * 64 + mb);
        float4 a1 = *(const float4*)(As + k * 64 + mb + 4);
        float4 w0 = *(const float4*)(Ws + k * 256 + nb);
        float4 w1 = *(const float4*)(Ws + k * 256 + nb + 4);
        float av[8] = {a0.x, a0.y, a0.z, a0.w, a1.x, a1.y, a1.z, a1.w};
        float wv[8] = {w0.x, w0.y, w0.z, w0.w, w1.x, w1.y, w1.z, w1.w};
        #pragma unroll
        for (int i = 0; i < 8; i++)
            #pragma unroll
            for (int j = 0; j < 8; j++)
                acc[i][j] = fmaf(av[i], wv[j], acc[i][j]);
    }

    float bias[8];
    #pragma unroll
    for (int j = 0; j < 8; j++)
        bias[j] = ba[n0 + nb + j] + bb[n0 + nb + j];

    #pragma unroll
    for (int i = 0; i < 8; i++) {
        float* orow = out + (size_t)(m0 + mb + i) * GG + n0 + nb;
        float4 o0 = make_float4(acc[i][0] + bias[0], acc[i][1] + bias[1],
                                acc[i][2] + bias[2], acc[i][3] + bias[3]);
        float4 o1 = make_float4(acc[i][4] + bias[4], acc[i][5] + bias[5],
                                acc[i][6] + bias[6], acc[i][7] + bias[7]);
        *(float4*)(orow) = o0;
        *(float4*)(orow + 4) = o1;
    }
}

// =====================================================================
// Recurrent LSTM layer: persistent per-cluster scan over S steps.
// cluster = 2 CTAs; cluster handles 8 batch rows; CTA owns 64 hidden
// columns (256 gate rows, W slice 128KB in SMEM) and a full replicated
// h copy (double-buffered). One barrier.cluster per step.
// grid = 128 CTAs (64 clusters), block = 256.
// =====================================================================
__global__ void __cluster_dims__(2, 1, 1) __launch_bounds__(256) lstm_kernel(
    const float* __restrict__ xp,    // [B, S, 4H] precomputed x-projection (+biases)
    const float* __restrict__ W_hh,  // [4H, H]
    float* __restrict__ hseq,        // [B, S, H] (layer 0) or unused
    float* __restrict__ hlast,       // [B, H]    (layer 1) or unused
    int store_seq)
{
    extern __shared__ float sm[];
    float4* Wt4 = (float4*)sm;            // [32 k4][256 j] float4 (k-interleaved)
    float* hsm  = sm + 32768;             // 2 buffers x [8 b][128 k]
    float* gsm  = sm + 34816;             // gates [256 j][stride 9]
    float* csm  = sm + 37120;             // c [64 cl][stride 9]

    const int tid   = threadIdx.x;
    const int rank  = blockIdx.x & 1;
    const int peer  = rank ^ 1;
    const int batch0 = (blockIdx.x >> 1) * 8;

    // gate-row mapping: thread j -> gate type gt = j>>6, local col = j&63
    const int gt    = tid >> 6;
    const int clw   = tid & 63;
    const int grow  = gt * 128 + rank * 64 + clw;   // global gate row in [0,512)

    // Load W_hh slice into SMEM (k-interleaved for LDS.128 in the main loop)
    {
        const float* wr = W_hh + (size_t)grow * HH;
        float* Wt = sm;
        #pragma unroll 4
        for (int k = 0; k < HH; k++)
            Wt[(k >> 2) * 1024 + tid * 4 + (k & 3)] = wr[k];
    }
    // zero h (both buffers) and c
    for (int i = tid; i < 2048; i += 256) hsm[i] = 0.0f;
    for (int i = tid; i < 64 * 9; i += 256) csm[i] = 0.0f;

    // all CTAs in cluster ready before anyone writes peer SMEM
    asm volatile("barrier.cluster.arrive.aligned;\n" ::: "memory");
    asm volatile("barrier.cluster.wait.aligned;\n" ::: "memory");

    const int cl  = tid & 63;
    const int bh  = tid >> 6;
    const int col = rank * 64 + cl;

    int buf = 0;
    for (int s = 0; s < SS; s++) {
        const float* Hc = hsm + buf * 1024;
        float* Hn = hsm + (buf ^ 1) * 1024;

        // prefetch this step's x-projection (consumed after the k-loop)
        float xpv[8];
        const float* xpp = xp + ((size_t)batch0 * SS + s) * GG + grow;
        #pragma unroll
        for (int b = 0; b < 8; b++)
            xpv[b] = xpp[(size_t)b * SS * GG];

        // gates[b, grow] = sum_k h[b,k] * W[grow,k]
        float acc[8];
        #pragma unroll
        for (int b = 0; b < 8; b++) acc[b] = 0.0f;

        #pragma unroll 4
        for (int k4 = 0; k4 < 32; k4++) {
            float4 w = Wt4[k4 * 256 + tid];
            #pragma unroll
            for (int b = 0; b < 8; b++) {
                float4 hv = *(const float4*)(Hc + b * 128 + k4 * 4);
                float t = fmaf(w.x, hv.x, acc[b]);
                t = fmaf(w.y, hv.y, t);
                t = fmaf(w.z, hv.z, t);
                acc[b] = fmaf(w.w, hv.w, t);
            }
        }

        #pragma unroll
        for (int b = 0; b < 8; b++)
            gsm[tid * 9 + b] = acc[b] + xpv[b];
        __syncthreads();

        // nonlinearity + state update: thread -> (col cl, 2 batch rows)
        #pragma unroll
        for (int bb = 0; bb < 2; bb++) {
            const int b = bh * 2 + bb;
            float gi = gsm[(cl) * 9 + b];
            float gf = gsm[(64 + cl) * 9 + b];
            float gg = gsm[(128 + cl) * 9 + b];
            float go = gsm[(192 + cl) * 9 + b];
            float iv = sigf(gi);
            float fv = sigf(gf);
            float gv = tanhf_fast(gg);
            float ov = sigf(go);
            float cc = fmaf(fv, csm[cl * 9 + b], iv * gv);
            csm[cl * 9 + b] = cc;
            float hh = ov * tanhf_fast(cc);

            // own copy
            Hn[b * 128 + col] = hh;
            // peer copy via DSMEM
            uint32_t la = (uint32_t)__cvta_generic_to_shared(Hn + b * 128 + col);
            uint32_t ra;
            asm("mapa.shared::cluster.u32 %0, %1, %2;" : "=r"(ra) : "r"(la), "r"(peer));
            asm volatile("st.shared::cluster.f32 [%0], %1;" :: "r"(ra), "f"(hh) : "memory");

            if (store_seq) {
                hseq[((size_t)(batch0 + b) * SS + s) * HH + col] = hh;
            } else if (s == SS - 1) {
                hlast[(batch0 + b) * HH + col] = hh;
            }
        }

        // one cluster barrier per step (double-buffered h makes this sufficient)
        asm volatile("barrier.cluster.arrive.aligned;\n" ::: "memory");
        asm volatile("barrier.cluster.wait.aligned;\n" ::: "memory");
        buf ^= 1;
    }
}

// =====================================================================
// Final FC: out[b,o] = relu(h1[b,:]) @ fc_w[o,:] + fc_b[o]
// =====================================================================
__global__ __launch_bounds__(64) void fc_kernel(
    const float* __restrict__ h1, const float* __restrict__ fcw,
    const float* __restrict__ fcb, float* __restrict__ out)
{
    __shared__ float hs[HH];
    const int b = blockIdx.x;
    const int o = threadIdx.x;
    hs[o]      = fmaxf(h1[b * HH + o], 0.0f);
    hs[o + 64] = fmaxf(h1[b * HH + o + 64], 0.0f);
    __syncthreads();
    float acc = fcb[o];
    const float* wr = fcw + o * HH;
    #pragma unroll 8
    for (int k = 0; k < HH; k++)
        acc = fmaf(hs[k], wr[k], acc);
    out[b * OO + o] = acc;
}

// =====================================================================
extern "C" void kernel_launch(void* const* d_in, const int* in_sizes, int n_in,
                              void* d_out, int out_size)
{
    (void)in_sizes; (void)n_in; (void)out_size;
    const float* x     = (const float*)d_in[0];
    const float* W_ih0 = (const float*)d_in[1];
    const float* W_hh0 = (const float*)d_in[2];
    const float* b_ih0 = (const float*)d_in[3];
    const float* b_hh0 = (const float*)d_in[4];
    const float* W_ih1 = (const float*)d_in[5];
    const float* W_hh1 = (const float*)d_in[6];
    const float* b_ih1 = (const float*)d_in[7];
    const float* b_hh1 = (const float*)d_in[8];
    const float* fc_w  = (const float*)d_in[9];
    const float* fc_b  = (const float*)d_in[10];
    float* out = (float*)d_out;

    float *xp, *h0, *h1;
    cudaGetSymbolAddress((void**)&xp, g_xp);
    cudaGetSymbolAddress((void**)&h0, g_h0);
    cudaGetSymbolAddress((void**)&h1, g_h1);

    const int PROJ0_SMEM = (64 + 256) * FF * 4;    // 81920
    const int PROJ1_SMEM = (64 + 256) * HH * 4;    // 163840
    const int LSTM_SMEM  = 37696 * 4;              // 150784

    cudaFuncSetAttribute(proj_kernel<FF>, cudaFuncAttributeMaxDynamicSharedMemorySize, PROJ0_SMEM);
    cudaFuncSetAttribute(proj_kernel<HH>, cudaFuncAttributeMaxDynamicSharedMemorySize, PROJ1_SMEM);
    cudaFuncSetAttribute(lstm_kernel, cudaFuncAttributeMaxDynamicSharedMemorySize, LSTM_SMEM);

    dim3 pgrid((BB * SS) / 64, 2);

    // Layer 0: input projection -> recurrent scan (writes h0 sequence)
    proj_kernel<FF><<<pgrid, 256, PROJ0_SMEM>>>(x, W_ih0, b_ih0, b_hh0, xp);
    lstm_kernel<<<128, 256, LSTM_SMEM>>>(xp, W_hh0, h0, nullptr, 1);

    // Layer 1: projection of h0 sequence -> recurrent scan (writes last h only)
    proj_kernel<HH><<<pgrid, 256, PROJ1_SMEM>>>(h0, W_ih1, b_ih1, b_hh1, xp);
    lstm_kernel<<<128, 256, LSTM_SMEM>>>(xp, W_hh1, nullptr, h1, 0);

    // FC head
    fc_kernel<<<BB, 64>>>(h1, fc_w, fc_b, out);
}

// round 2
// speedup vs baseline: 1.1144x; 1.1144x over previous
#include <cuda_runtime.h>
#include <cstdint>

typedef unsigned long long u64;

#define BB 512
#define SS 512
#define FF 64
#define HH 128
#define GG 512   // 4*H
#define OO 64

// ---- scratch (static __device__ globals: allocation-free rule) ----
__device__ float g_xp[(size_t)BB * SS * GG];   // 512 MB, reused across layers
__device__ float g_h0[(size_t)BB * SS * HH];   // 64 MB  (layer0 hidden sequence)
__device__ float g_h1[BB * HH];                // layer1 last hidden

// ---- packed f32x2 helpers (sm_103a FFMA2 path) ----
__device__ __forceinline__ u64 ffma2(u64 a, u64 b, u64 c) {
    u64 d; asm("fma.rn.f32x2 %0,%1,%2,%3;" : "=l"(d) : "l"(a), "l"(b), "l"(c)); return d;
}
__device__ __forceinline__ u64 fadd2(u64 a, u64 b) {
    u64 d; asm("add.rn.f32x2 %0,%1,%2;" : "=l"(d) : "l"(a), "l"(b)); return d;
}
__device__ __forceinline__ u64 pack2(float x) {
    u64 d; asm("mov.b64 %0,{%1,%1};" : "=l"(d) : "f"(x)); return d;
}
__device__ __forceinline__ u64 pack2b(float x, float y) {
    u64 d; asm("mov.b64 %0,{%1,%2};" : "=l"(d) : "f"(x), "f"(y)); return d;
}
__device__ __forceinline__ float2 unpack2(u64 v) {
    float2 r; asm("mov.b64 {%0,%1},%2;" : "=f"(r.x), "=f"(r.y) : "l"(v)); return r;
}

__device__ __forceinline__ float sigf(float x) {
    return __fdividef(1.0f, 1.0f + __expf(-x));
}
__device__ __forceinline__ float tanhf_fast(float x) {
    return 1.0f - __fdividef(2.0f, __expf(2.0f * x) + 1.0f);
}

// =====================================================================
// Projection GEMM (FFMA2): out[M,512] = A[M,K] @ W[512,K]^T + ba + bb
// grid = (M/64, 2), block = 256. SMEM: As[K][64], Ws[K][256]
// =====================================================================
template <int K>
__global__ __launch_bounds__(256) void proj_kernel(
    const float* __restrict__ A, const float* __restrict__ W,
    const float* __restrict__ ba, const float* __restrict__ bb,
    float* __restrict__ out)
{
    extern __shared__ float sm[];
    float* As = sm;            // [K][64]
    float* Ws = sm + K * 64;   // [K][256]

    const int tid = threadIdx.x;
    const int m0 = blockIdx.x * 64;
    const int n0 = blockIdx.y * 256;

    {
        const int r = tid & 63;
        for (int k = (tid >> 6); k < K; k += 4)
            As[k * 64 + r] = A[(size_t)(m0 + r) * K + k];
    }
    {
        const float* wrow = W + (size_t)(n0 + tid) * K;
        #pragma unroll 4
        for (int k = 0; k < K; k++)
            Ws[k * 256 + tid] = wrow[k];
    }
    __syncthreads();

    const int tx = tid & 31, ty = tid >> 5;
    const int mb = ty * 8, nb = tx * 8;

    u64 acc[8][4];
    #pragma unroll
    for (int i = 0; i < 8; i++)
        #pragma unroll
        for (int j = 0; j < 4; j++) acc[i][j] = 0ull;

    #pragma unroll 2
    for (int k = 0; k < K; k++) {
        float4 a0 = *(const float4*)(As + k * 64 + mb);
        float4 a1 = *(const float4*)(As + k * 64 + mb + 4);
        ulonglong2 wA = *(const ulonglong2*)(Ws + k * 256 + nb);
        ulonglong2 wB = *(const ulonglong2*)(Ws + k * 256 + nb + 4);
        float av[8] = {a0.x, a0.y, a0.z, a0.w, a1.x, a1.y, a1.z, a1.w};
        u64 wv[4] = {wA.x, wA.y, wB.x, wB.y};
        #pragma unroll
        for (int i = 0; i < 8; i++) {
            u64 ap = pack2(av[i]);
            #pragma unroll
            for (int j = 0; j < 4; j++)
                acc[i][j] = ffma2(ap, wv[j], acc[i][j]);
        }
    }

    u64 bias[4];
    #pragma unroll
    for (int j = 0; j < 4; j++) {
        int n = n0 + nb + 2 * j;
        bias[j] = pack2b(ba[n] + bb[n], ba[n + 1] + bb[n + 1]);
    }

    #pragma unroll
    for (int i = 0; i < 8; i++) {
        float* orow = out + (size_t)(m0 + mb + i) * GG + n0 + nb;
        ulonglong2 s0, s1;
        s0.x = fadd2(acc[i][0], bias[0]);
        s0.y = fadd2(acc[i][1], bias[1]);
        s1.x = fadd2(acc[i][2], bias[2]);
        s1.y = fadd2(acc[i][3], bias[3]);
        *(ulonglong2*)(orow) = s0;
        *(ulonglong2*)(orow + 4) = s1;
    }
}

// =====================================================================
// Recurrent LSTM layer (FFMA2, 512 threads, cluster of 2 CTAs).
// Cluster handles 8 batch rows; each CTA owns 64 hidden columns
// (256 gate rows, 128KB W in SMEM) + full replicated double-buffered h.
// GEMM split: thread -> (2 gate rows, 1/4 of k). Partials reduced via gsm.
// grid = 128 CTAs (64 clusters), block = 512.
// =====================================================================
__global__ void __cluster_dims__(2, 1, 1) __launch_bounds__(512) lstm_kernel(
    const float* __restrict__ xp,    // [B, S, 4H]
    const float* __restrict__ W_hh,  // [4H, H]
    float* __restrict__ hseq,        // [B, S, H]  (layer 0)
    float* __restrict__ hlast,       // [B, H]     (layer 1)
    int store_seq)
{
    extern __shared__ float sm[];
    float4* Wt4 = (float4*)sm;            // [32 k4][256 r] float4
    float* hsm  = sm + 32768;             // 2 x [2 g][128 k][4 b] = 2 x 1024
    float* gsm  = sm + 34816;             // [4 kq][256 r][stride 9]

    const int tid    = threadIdx.x;
    const int rank   = blockIdx.x & 1;
    const int peer   = rank ^ 1;
    const int batch0 = (blockIdx.x >> 1) * 8;

    // ---- load W slice: entry e = k4*256 + r  ->  W_hh[grow(r)][k4*4..+3]
    for (int e = tid; e < 8192; e += 512) {
        int k4 = e >> 8, r = e & 255;
        int grow = (r >> 6) * 128 + rank * 64 + (r & 63);
        Wt4[e] = *(const float4*)(W_hh + (size_t)grow * HH + k4 * 4);
    }
    for (int i = tid; i < 2048; i += 512) hsm[i] = 0.0f;

    asm volatile("barrier.cluster.arrive.aligned;\n" ::: "memory");
    asm volatile("barrier.cluster.wait.aligned;\n" ::: "memory");

    // GEMM mapping: kq = k-quarter, rows rr and rr+128
    const int kq = tid >> 7;
    const int rr = tid & 127;
    // update mapping: one (col, batch) per thread
    const int ub  = tid >> 6;        // batch 0..7
    const int ucl = tid & 63;        // local col
    const int col = rank * 64 + ucl;

    float creg = 0.0f;
    int buf = 0;

    for (int s = 0; s < SS; s++) {
        const float* Hc = hsm + buf * 1024;
        float* Hn = hsm + (buf ^ 1) * 1024;

        // prefetch this step's x-projection (used in update phase)
        float xv[4];
        {
            const float* xpp = xp + ((size_t)(batch0 + ub) * SS + s) * GG + rank * 64 + ucl;
            #pragma unroll
            for (int gt = 0; gt < 4; gt++) xv[gt] = xpp[gt * 128];
        }

        // ---- partial gate GEMM over this thread's k-quarter, 2 rows
        u64 a00 = 0, a01 = 0, a02 = 0, a03 = 0;
        u64 a10 = 0, a11 = 0, a12 = 0, a13 = 0;

        #pragma unroll 4
        for (int k4 = 0; k4 < 8; k4++) {
            const int k4g = kq * 8 + k4;
            float4 w0 = Wt4[k4g * 256 + rr];
            float4 w1 = Wt4[k4g * 256 + rr + 128];
            const float* wf0 = (const float*)&w0;
            const float* wf1 = (const float*)&w1;
            #pragma unroll
            for (int j = 0; j < 4; j++) {
                const int k = k4g * 4 + j;
                ulonglong2 hA = *(const ulonglong2*)(Hc + k * 4);        // b0..b3
                ulonglong2 hB = *(const ulonglong2*)(Hc + 512 + k * 4);  // b4..b7
                u64 wp0 = pack2(wf0[j]);
                u64 wp1 = pack2(wf1[j]);
                a00 = ffma2(hA.x, wp0, a00);
                a01 = ffma2(hA.y, wp0, a01);
                a02 = ffma2(hB.x, wp0, a02);
                a03 = ffma2(hB.y, wp0, a03);
                a10 = ffma2(hA.x, wp1, a10);
                a11 = ffma2(hA.y, wp1, a11);
                a12 = ffma2(hB.x, wp1, a12);
                a13 = ffma2(hB.y, wp1, a13);
            }
        }

        // write partials: gsm[kq][row][b]
        {
            float* g0 = gsm + kq * 2304 + rr * 9;
            float* g1 = gsm + kq * 2304 + (rr + 128) * 9;
            float2 v;
            v = unpack2(a00); g0[0] = v.x; g0[1] = v.y;
            v = unpack2(a01); g0[2] = v.x; g0[3] = v.y;
            v = unpack2(a02); g0[4] = v.x; g0[5] = v.y;
            v = unpack2(a03); g0[6] = v.x; g0[7] = v.y;
            v = unpack2(a10); g1[0] = v.x; g1[1] = v.y;
            v = unpack2(a11); g1[2] = v.x; g1[3] = v.y;
            v = unpack2(a12); g1[4] = v.x; g1[5] = v.y;
            v = unpack2(a13); g1[6] = v.x; g1[7] = v.y;
        }
        __syncthreads();

        // ---- nonlinearity + state update: thread -> (col, batch ub)
        {
            float g4[4];
            #pragma unroll
            for (int gt = 0; gt < 4; gt++) {
                const int row = gt * 64 + ucl;
                float v = xv[gt];
                v += gsm[row * 9 + ub];
                v += gsm[2304 + row * 9 + ub];
                v += gsm[4608 + row * 9 + ub];
                v += gsm[6912 + row * 9 + ub];
                g4[gt] = v;
            }
            float iv = sigf(g4[0]);
            float fv = sigf(g4[1]);
            float gv = tanhf_fast(g4[2]);
            float ov = sigf(g4[3]);
            creg = fmaf(fv, creg, iv * gv);
            float hh = ov * tanhf_fast(creg);

            const int hoff = (ub >> 2) * 512 + col * 4 + (ub & 3);
            Hn[hoff] = hh;
            uint32_t la = (uint32_t)__cvta_generic_to_shared(Hn + hoff);
            uint32_t ra;
            asm("mapa.shared::cluster.u32 %0, %1, %2;" : "=r"(ra) : "r"(la), "r"(peer));
            asm volatile("st.shared::cluster.f32 [%0], %1;" :: "r"(ra), "f"(hh) : "memory");

            if (store_seq) {
                hseq[((size_t)(batch0 + ub) * SS + s) * HH + col] = hh;
            } else if (s == SS - 1) {
                hlast[(batch0 + ub) * HH + col] = hh;
            }
        }

        asm volatile("barrier.cluster.arrive.aligned;\n" ::: "memory");
        asm volatile("barrier.cluster.wait.aligned;\n" ::: "memory");
        buf ^= 1;
    }
}

// =====================================================================
// Final FC: out[b,o] = relu(h1[b,:]) @ fc_w[o,:] + fc_b[o]
// =====================================================================
__global__ __launch_bounds__(64) void fc_kernel(
    const float* __restrict__ h1, const float* __restrict__ fcw,
    const float* __restrict__ fcb, float* __restrict__ out)
{
    __shared__ float hs[HH];
    const int b = blockIdx.x;
    const int o = threadIdx.x;
    hs[o]      = fmaxf(h1[b * HH + o], 0.0f);
    hs[o + 64] = fmaxf(h1[b * HH + o + 64], 0.0f);
    __syncthreads();
    float acc = fcb[o];
    const float* wr = fcw + o * HH;
    #pragma unroll 8
    for (int k = 0; k < HH; k++)
        acc = fmaf(hs[k], wr[k], acc);
    out[b * OO + o] = acc;
}

// =====================================================================
extern "C" void kernel_launch(void* const* d_in, const int* in_sizes, int n_in,
                              void* d_out, int out_size)
{
    (void)in_sizes; (void)n_in; (void)out_size;
    const float* x     = (const float*)d_in[0];
    const float* W_ih0 = (const float*)d_in[1];
    const float* W_hh0 = (const float*)d_in[2];
    const float* b_ih0 = (const float*)d_in[3];
    const float* b_hh0 = (const float*)d_in[4];
    const float* W_ih1 = (const float*)d_in[5];
    const float* W_hh1 = (const float*)d_in[6];
    const float* b_ih1 = (const float*)d_in[7];
    const float* b_hh1 = (const float*)d_in[8];
    const float* fc_w  = (const float*)d_in[9];
    const float* fc_b  = (const float*)d_in[10];
    float* out = (float*)d_out;

    float *xp, *h0, *h1;
    cudaGetSymbolAddress((void**)&xp, g_xp);
    cudaGetSymbolAddress((void**)&h0, g_h0);
    cudaGetSymbolAddress((void**)&h1, g_h1);

    const int PROJ0_SMEM = (64 + 256) * FF * 4;    // 81920
    const int PROJ1_SMEM = (64 + 256) * HH * 4;    // 163840
    const int LSTM_SMEM  = (32768 + 2048 + 9216) * 4;  // 176128

    cudaFuncSetAttribute(proj_kernel<FF>, cudaFuncAttributeMaxDynamicSharedMemorySize, PROJ0_SMEM);
    cudaFuncSetAttribute(proj_kernel<HH>, cudaFuncAttributeMaxDynamicSharedMemorySize, PROJ1_SMEM);
    cudaFuncSetAttribute(lstm_kernel, cudaFuncAttributeMaxDynamicSharedMemorySize, LSTM_SMEM);

    dim3 pgrid((BB * SS) / 64, 2);

    // Layer 0
    proj_kernel<FF><<<pgrid, 256, PROJ0_SMEM>>>(x, W_ih0, b_ih0, b_hh0, xp);
    lstm_kernel<<<128, 512, LSTM_SMEM>>>(xp, W_hh0, h0, nullptr, 1);

    // Layer 1
    proj_kernel<HH><<<pgrid, 256, PROJ1_SMEM>>>(h0, W_ih1, b_ih1, b_hh1, xp);
    lstm_kernel<<<128, 512, LSTM_SMEM>>>(xp, W_hh1, nullptr, h1, 0);

    // FC head
    fc_kernel<<<BB, 64>>>(h1, fc_w, fc_b, out);
}